// round 10
// baseline (speedup 1.0000x reference)
#include <cuda_runtime.h>
#include <math.h>
#include <stdint.h>

#define TLEN  32000
#define BATCH 8
#define RES   32
#define SKIPC 32
#define TT    128
#define TLT   256   // threads for k_layer (8 warps)

typedef unsigned long long ull;

// ==================== helpers ==============================================
__device__ __forceinline__ uint32_t smem_u32(const void* p) {
    uint32_t a;
    asm("{ .reg .u64 t; cvta.to.shared.u64 t, %1; cvt.u32.u64 %0, t; }" : "=r"(a) : "l"(p));
    return a;
}
__device__ __forceinline__ void sts32(uint32_t a, uint32_t v) {
    asm volatile("st.shared.b32 [%0], %1;" :: "r"(a), "r"(v));
}
__device__ __forceinline__ void ldsm4(uint32_t& r0, uint32_t& r1, uint32_t& r2, uint32_t& r3,
                                      uint32_t addr) {
    asm volatile("ldmatrix.sync.aligned.m8n8.x4.shared.b16 {%0,%1,%2,%3}, [%4];"
                 : "=r"(r0), "=r"(r1), "=r"(r2), "=r"(r3) : "r"(addr));
}
// pack {lo=v0, hi=v1} as bf16x2 (RN)
__device__ __forceinline__ uint32_t pack_bf16x2(float v0, float v1) {
    uint32_t r;
    asm("cvt.rn.bf16x2.f32 %0, %1, %2;" : "=r"(r) : "f"(v1), "f"(v0));
    return r;
}
__device__ __forceinline__ void mma_bf16(float* c,
                                         uint32_t a0, uint32_t a1, uint32_t a2, uint32_t a3,
                                         uint32_t b0, uint32_t b1) {
    asm volatile("mma.sync.aligned.m16n8k16.row.col.f32.bf16.bf16.f32 "
                 "{%0,%1,%2,%3}, {%4,%5,%6,%7}, {%8,%9}, {%0,%1,%2,%3};"
                 : "+f"(c[0]), "+f"(c[1]), "+f"(c[2]), "+f"(c[3])
                 : "r"(a0), "r"(a1), "r"(a2), "r"(a3), "r"(b0), "r"(b1));
}
__device__ __forceinline__ float ftanh(float x) {
    float e = __expf(-2.f * fabsf(x));
    float r = __fdividef(1.f - e, 1.f + e);
    return copysignf(r, x);
}
__device__ __forceinline__ float fsigm(float x) {
    return __fdividef(1.f, 1.f + __expf(-x));
}
// split pair into bf16 hi pack + residual lo pack
__device__ __forceinline__ void split_pair(float v0, float v1, uint32_t& hi, uint32_t& lo) {
    hi = pack_bf16x2(v0, v1);
    float h0 = __uint_as_float((hi & 0xFFFFu) << 16);
    float h1 = __uint_as_float(hi & 0xFFFF0000u);
    lo = pack_bf16x2(v0 - h0, v1 - h1);
}
__device__ __forceinline__ float bfl(uint32_t x) { return __uint_as_float(x << 16); }
__device__ __forceinline__ float bfh(uint32_t x) { return __uint_as_float(x & 0xFFFF0000u); }

// ==================== device scratch =======================================
__device__ uint32_t g_bh0[BATCH * TLEN * 16];
__device__ uint32_t g_bl0[BATCH * TLEN * 16];
__device__ uint32_t g_bh1[BATCH * TLEN * 16];
__device__ uint32_t g_bl1[BATCH * TLEN * 16];
__device__ float g_skip[BATCH * TLEN * SKIPC];   // time-major [b][t][32]
__device__ uint32_t g_w1h[10][64 * 52];
__device__ uint32_t g_w1l[10][64 * 52];
__device__ uint32_t g_w2h[10][64 * 20];
__device__ uint32_t g_w2l[10][64 * 20];

// ==================== weight prep ==========================================
__global__ __launch_bounds__(TT) void k_wprep(const float* __restrict__ res_w1,
                                              const float* __restrict__ res_w2) {
    int L = blockIdx.x;
    const float* w1 = res_w1 + (size_t)L * 64 * 32 * 3;
    const float* w2 = res_w2 + (size_t)L * 64 * 32;
    int tid = threadIdx.x;
    for (int i = tid; i < 64 * 48; i += TT) {
        int oc = i / 48, pj = i % 48;
        int k0 = 2 * pj;
        int tap = k0 >> 5, ic = k0 & 31;
        float v0 = w1[oc * 96 + ic * 3 + tap];
        float v1 = w1[oc * 96 + (ic + 1) * 3 + tap];
        uint32_t hi, lo;
        split_pair(v0, v1, hi, lo);
        g_w1h[L][oc * 52 + pj] = hi;
        g_w1l[L][oc * 52 + pj] = lo;
    }
    for (int i = tid; i < 64 * 16; i += TT) {
        int oc = i / 16, icp = i % 16;
        float v0 = w2[oc * 32 + 2 * icp];
        float v1 = w2[oc * 32 + 2 * icp + 1];
        uint32_t hi, lo;
        split_pair(v0, v1, hi, lo);
        g_w2h[L][oc * 20 + icp] = hi;
        g_w2l[L][oc * 20 + icp] = lo;
    }
}

// ==================== front conv -> bf16 hi/lo t-major; zero skip ==========
__global__ __launch_bounds__(TT) void k_front(const float* __restrict__ x,
                                              const float* __restrict__ w) {
    int b = blockIdx.y;
    int t = blockIdx.x * TT + threadIdx.x;
    if (t >= TLEN) return;
    const float* xb = x + b * TLEN;
    float x0 = xb[t];
    float x1 = (t >= 1) ? xb[t - 1] : 0.f;
    float x2 = (t >= 2) ? xb[t - 2] : 0.f;
    size_t base = (size_t)(b * TLEN + t) * 16;
    float* sk = g_skip + (size_t)(b * TLEN + t) * 32;
#pragma unroll
    for (int p = 0; p < 16; p++) {
        int oc = 2 * p;
        float v0 = fmaf(w[oc * 3 + 0], x2, fmaf(w[oc * 3 + 1], x1, w[oc * 3 + 2] * x0));
        float v1 = fmaf(w[(oc + 1) * 3 + 0], x2,
                   fmaf(w[(oc + 1) * 3 + 1], x1, w[(oc + 1) * 3 + 2] * x0));
        uint32_t hi, lo;
        split_pair(v0, v1, hi, lo);
        g_bh0[base + p] = hi;
        g_bl0[base + p] = lo;
        sk[oc] = 0.f;
        sk[oc + 1] = 0.f;
    }
}

// ==================== residual layer =======================================
#define STRA 208
#define STRG 80
#define SO_AH 0
#define SO_AL (SO_AH + 128 * STRA)       // 26624
#define SO_BH (SO_AL + 128 * STRA)       // 53248
#define SO_BL (SO_BH + 64 * STRA)        // 66560
#define SO_W2H (SO_BL + 64 * STRA)       // 79872
#define SO_W2L (SO_W2H + 64 * STRG)      // 84992
#define SMEM_LAYER_BYTES (SO_W2L + 64 * STRG)  // 90112

// fused 3-combo conv GEMM: acc += AH·BH^T + AL·BH^T + AH·BL^T
__device__ __forceinline__ void gemm_fused(uint32_t aHB, uint32_t aLB,
                                           uint32_t bHB, uint32_t bLB,
                                           int stride, int nk16, float acc[8][4],
                                           int wid, int lid) {
    int lr = lid & 7;
    int aRowOff = lr + ((lid >> 3) & 1) * 8;
    int aKOff = (lid >> 4) * 8;
    int bRowOff = lr + (lid >> 4) * 8;
    int bKOff = ((lid >> 3) & 1) * 8;
    uint32_t aH = aHB + (uint32_t)((16 * wid + aRowOff) * stride + aKOff * 2);
    uint32_t aL = aLB + (uint32_t)((16 * wid + aRowOff) * stride + aKOff * 2);
    uint32_t bH0 = bHB + (uint32_t)(bRowOff * stride + bKOff * 2);
    uint32_t bL0 = bLB + (uint32_t)(bRowOff * stride + bKOff * 2);
#pragma unroll
    for (int k = 0; k < nk16; k++) {
        uint32_t ka = (uint32_t)(k * 32);
        uint32_t ah0, ah1, ah2, ah3, al0, al1, al2, al3;
        ldsm4(ah0, ah1, ah2, ah3, aH + ka);
        ldsm4(al0, al1, al2, al3, aL + ka);
#pragma unroll
        for (int np = 0; np < 4; np++) {
            uint32_t off = (uint32_t)(16 * np * stride) + ka;
            uint32_t bh0, bh1, bh2, bh3, bl0, bl1, bl2, bl3;
            ldsm4(bh0, bh1, bh2, bh3, bH0 + off);
            ldsm4(bl0, bl1, bl2, bl3, bL0 + off);
            mma_bf16(acc[2 * np],     ah0, ah1, ah2, ah3, bh0, bh1);
            mma_bf16(acc[2 * np + 1], ah0, ah1, ah2, ah3, bh2, bh3);
            mma_bf16(acc[2 * np],     al0, al1, al2, al3, bh0, bh1);
            mma_bf16(acc[2 * np + 1], al0, al1, al2, al3, bh2, bh3);
            mma_bf16(acc[2 * np],     ah0, ah1, ah2, ah3, bl0, bl1);
            mma_bf16(acc[2 * np + 1], ah0, ah1, ah2, ah3, bl2, bl3);
        }
    }
}

__global__ __launch_bounds__(TLT, 2) void k_layer(const uint32_t* __restrict__ hinH,
                                                  const uint32_t* __restrict__ hinL,
                                                  uint32_t* __restrict__ houtH,
                                                  uint32_t* __restrict__ houtL,
                                                  const uint32_t* __restrict__ w1h,
                                                  const uint32_t* __restrict__ w1l,
                                                  const uint32_t* __restrict__ w2h,
                                                  const uint32_t* __restrict__ w2l,
                                                  int d) {
    extern __shared__ __align__(16) char smem[];
    uint32_t sb = smem_u32(smem);
    int tid = threadIdx.x;
    int wid = tid >> 5;
    int lid = tid & 31;
    int qr = lid >> 2;
    int qc = lid & 3;
    int b = blockIdx.y;
    int t0 = blockIdx.x * 128;

    // ---- stage A: vectorized copy; 768 copy-units of 64B (row,tap,arr)
    {
        const uint4 zero4 = make_uint4(0, 0, 0, 0);
#pragma unroll
        for (int u = 0; u < 3; u++) {
            int idx = tid + u * TLT;
            int m = idx / 6;
            int j = idx % 6;
            int tap = j >> 1;
            int arr = j & 1;
            int tt = t0 + m - (2 - tap) * d;
            uint32_t dst = (uint32_t)((arr ? SO_AL : SO_AH) + m * STRA + tap * 64);
            if (tt >= 0) {
                const uint32_t* src = (arr ? hinL : hinH) + (size_t)(b * TLEN + tt) * 16;
                const uint4* s4 = reinterpret_cast<const uint4*>(src);
#pragma unroll
                for (int q = 0; q < 4; q++)
                    *reinterpret_cast<uint4*>(smem + dst + q * 16) = s4[q];
            } else {
#pragma unroll
                for (int q = 0; q < 4; q++)
                    *reinterpret_cast<uint4*>(smem + dst + q * 16) = zero4;
            }
        }
    }
    // ---- weights: linear uint4 copies
    {
        const uint4* s1h = reinterpret_cast<const uint4*>(w1h);
        const uint4* s1l = reinterpret_cast<const uint4*>(w1l);
        uint4* d1h = reinterpret_cast<uint4*>(smem + SO_BH);
        uint4* d1l = reinterpret_cast<uint4*>(smem + SO_BL);
        for (int i = tid; i < 64 * 13; i += TLT) {
            d1h[i] = s1h[i];
            d1l[i] = s1l[i];
        }
        const uint4* s2h = reinterpret_cast<const uint4*>(w2h);
        const uint4* s2l = reinterpret_cast<const uint4*>(w2l);
        uint4* d2h = reinterpret_cast<uint4*>(smem + SO_W2H);
        uint4* d2l = reinterpret_cast<uint4*>(smem + SO_W2L);
        for (int i = tid; i < 64 * 5; i += TLT) {
            d2h[i] = s2h[i];
            d2l[i] = s2l[i];
        }
    }
    __syncthreads();

    // ---- conv GEMM: fused 3-combo
    float acc[8][4];
#pragma unroll
    for (int n = 0; n < 8; n++)
#pragma unroll
        for (int j = 0; j < 4; j++) acc[n][j] = 0.f;

    gemm_fused(sb + SO_AH, sb + SO_AL, sb + SO_BH, sb + SO_BL, STRA, 6, acc, wid, lid);

    // ---- gating entirely in registers -> A fragments for the 1x1 GEMM
    // gv[n][j]: n-tile n (ic cols 8n+2qc..), j: {row qr k0, k1, row qr+8 k0, k1}
    float gv[4][4];
#pragma unroll
    for (int n = 0; n < 4; n++)
#pragma unroll
        for (int j = 0; j < 4; j++)
            gv[n][j] = ftanh(acc[n][j]) * fsigm(acc[n + 4][j]);

    uint32_t aH[2][4], aL[2][4];
#pragma unroll
    for (int kk = 0; kk < 2; kk++) {
        split_pair(gv[2 * kk][0],     gv[2 * kk][1],     aH[kk][0], aL[kk][0]);
        split_pair(gv[2 * kk][2],     gv[2 * kk][3],     aH[kk][1], aL[kk][1]);
        split_pair(gv[2 * kk + 1][0], gv[2 * kk + 1][1], aH[kk][2], aL[kk][2]);
        split_pair(gv[2 * kk + 1][2], gv[2 * kk + 1][3], aH[kk][3], aL[kk][3]);
    }

    // ---- 1x1 GEMM: A from registers, B (W2) via ldmatrix; 3 combos
    float acc2[8][4];
#pragma unroll
    for (int n = 0; n < 8; n++)
#pragma unroll
        for (int j = 0; j < 4; j++) acc2[n][j] = 0.f;
    {
        int lr = lid & 7;
        int bRowOff = lr + (lid >> 4) * 8;
        int bKOff = ((lid >> 3) & 1) * 8;
        uint32_t w2H0 = sb + SO_W2H + (uint32_t)(bRowOff * STRG + bKOff * 2);
        uint32_t w2L0 = sb + SO_W2L + (uint32_t)(bRowOff * STRG + bKOff * 2);
#pragma unroll
        for (int kk = 0; kk < 2; kk++) {
            uint32_t ka = (uint32_t)(kk * 32);
#pragma unroll
            for (int np = 0; np < 4; np++) {
                uint32_t off = (uint32_t)(16 * np * STRG) + ka;
                uint32_t bh0, bh1, bh2, bh3, bl0, bl1, bl2, bl3;
                ldsm4(bh0, bh1, bh2, bh3, w2H0 + off);
                ldsm4(bl0, bl1, bl2, bl3, w2L0 + off);
                mma_bf16(acc2[2 * np],     aH[kk][0], aH[kk][1], aH[kk][2], aH[kk][3], bh0, bh1);
                mma_bf16(acc2[2 * np + 1], aH[kk][0], aH[kk][1], aH[kk][2], aH[kk][3], bh2, bh3);
                mma_bf16(acc2[2 * np],     aL[kk][0], aL[kk][1], aL[kk][2], aL[kk][3], bh0, bh1);
                mma_bf16(acc2[2 * np + 1], aL[kk][0], aL[kk][1], aL[kk][2], aL[kk][3], bh2, bh3);
                mma_bf16(acc2[2 * np],     aH[kk][0], aH[kk][1], aH[kk][2], aH[kk][3], bl0, bl1);
                mma_bf16(acc2[2 * np + 1], aH[kk][0], aH[kk][1], aH[kk][2], aH[kk][3], bl2, bl3);
            }
        }
    }

    // ---- epilogue: residual from A(tap2) + z -> hout; skip (t-major) += z
#pragma unroll
    for (int rh = 0; rh < 2; rh++) {
        int rowA = 16 * wid + qr + 8 * rh;
        int t = t0 + rowA;
        size_t obase = (size_t)(b * TLEN + t) * 16;
        float2* sk = reinterpret_cast<float2*>(g_skip + (size_t)(b * TLEN + t) * 32);
#pragma unroll
        for (int n = 0; n < 4; n++) {
            int c = 8 * n + 2 * qc;
            uint32_t hh = *reinterpret_cast<uint32_t*>(smem + SO_AH + rowA * STRA + (64 + c) * 2);
            uint32_t ll = *reinterpret_cast<uint32_t*>(smem + SO_AL + rowA * STRA + (64 + c) * 2);
            float r0 = bfl(hh) + bfl(ll) + acc2[n][2 * rh + 0];
            float r1 = bfh(hh) + bfh(ll) + acc2[n][2 * rh + 1];
            uint32_t hi, lo;
            split_pair(r0, r1, hi, lo);
            houtH[obase + (c >> 1)] = hi;
            houtL[obase + (c >> 1)] = lo;
        }
#pragma unroll
        for (int n = 4; n < 8; n++) {
            int c = 8 * (n - 4) + 2 * qc;
            float2 v = sk[c >> 1];
            v.x += acc2[n][2 * rh + 0];
            v.y += acc2[n][2 * rh + 1];
            sk[c >> 1] = v;
        }
    }
}

// ==================== fused post chain =====================================
// tanh(skip) -> conv32->16 tanh -> conv16->8 tanh -> conv8->1 tanh -> Volterra
// One block = 128 output samples, halo = 21 samples, all stages in SMEM.
__global__ __launch_bounds__(TT) void k_post(const float* __restrict__ post2_w,
                                             const float* __restrict__ post3_w,
                                             const float* __restrict__ post4_w,
                                             const float* __restrict__ vnn1_w,
                                             const float* __restrict__ vnn2_w,
                                             float* __restrict__ out) {
    __shared__ float ts[149 * 33];     // t = t0-21+r, stride 33
    __shared__ float p2s[147 * 17];    // t = t0-19+r, stride 17
    __shared__ float p3s[145 * 9];     // t = t0-17+r, stride 9
    __shared__ float p4s[143];         // t = t0-15+r
    __shared__ float w2s[3][32][16];
    __shared__ float w3s[3][16][8];
    __shared__ float w4s[3][8];
    __shared__ float v1s[16];
    __shared__ float v2s[6][16];

    int tid = threadIdx.x;
    int b = blockIdx.y;
    int t0 = blockIdx.x * TT;

    // weights
    for (int i = tid; i < 16 * 32 * 3; i += TT) {
        int oc = i / 96, r = i % 96, ic = r / 3, k = r % 3;
        w2s[k][ic][oc] = post2_w[i];
    }
    for (int i = tid; i < 8 * 16 * 3; i += TT) {
        int oc = i / 48, r = i % 48, ic = r / 3, k = r % 3;
        w3s[k][ic][oc] = post3_w[i];
    }
    if (tid < 24) w4s[tid % 3][tid / 3] = post4_w[tid];
    if (tid < 16) v1s[tid] = vnn1_w[tid];
    if (tid >= 32 && tid < 128) {
        int i = tid - 32;
        v2s[i / 16][i % 16] = vnn2_w[i];
    }

    // stage ts = tanh(skip), zero for t<0
    for (int i = tid; i < 149 * 8; i += TT) {
        int r = i >> 3, c4 = i & 7;
        int t = t0 - 21 + r;
        float4 v = make_float4(0.f, 0.f, 0.f, 0.f);
        if (t >= 0)
            v = *reinterpret_cast<const float4*>(g_skip + (size_t)(b * TLEN + t) * 32 + c4 * 4);
        float* dst = &ts[r * 33 + c4 * 4];
        dst[0] = ftanh(v.x);
        dst[1] = ftanh(v.y);
        dst[2] = ftanh(v.z);
        dst[3] = ftanh(v.w);
    }
    __syncthreads();

    // p2 = tanh(conv3(ts)), rows 0..146
    for (int r = tid; r < 147; r += TT) {
        float acc[16];
#pragma unroll
        for (int o = 0; o < 16; o++) acc[o] = 0.f;
#pragma unroll
        for (int k = 0; k < 3; k++) {
            const float* tr = &ts[(r + k) * 33];
#pragma unroll
            for (int ic = 0; ic < 32; ic++) {
                float v = tr[ic];
#pragma unroll
                for (int o = 0; o < 16; o++)
                    acc[o] = fmaf(v, w2s[k][ic][o], acc[o]);
            }
        }
#pragma unroll
        for (int o = 0; o < 16; o++) p2s[r * 17 + o] = ftanh(acc[o]);
    }
    __syncthreads();

    // p3 = tanh(conv3(p2)), rows 0..144
    for (int r = tid; r < 145; r += TT) {
        float acc[8];
#pragma unroll
        for (int o = 0; o < 8; o++) acc[o] = 0.f;
#pragma unroll
        for (int k = 0; k < 3; k++) {
            const float* pr = &p2s[(r + k) * 17];
#pragma unroll
            for (int ic = 0; ic < 16; ic++) {
                float v = pr[ic];
#pragma unroll
                for (int o = 0; o < 8; o++)
                    acc[o] = fmaf(v, w3s[k][ic][o], acc[o]);
            }
        }
#pragma unroll
        for (int o = 0; o < 8; o++) p3s[r * 9 + o] = ftanh(acc[o]);
    }
    __syncthreads();

    // p4 = tanh(conv3(p3)), rows 0..142
    for (int r = tid; r < 143; r += TT) {
        float a = 0.f;
#pragma unroll
        for (int k = 0; k < 3; k++) {
            const float* pr = &p3s[(r + k) * 9];
#pragma unroll
            for (int ic = 0; ic < 8; ic++)
                a = fmaf(pr[ic], w4s[k][ic], a);
        }
        p4s[r] = ftanh(a);
    }
    __syncthreads();

    // Volterra head: t = t0 + tid; pv[k] = p4[t-15+k] = p4s[tid + k]
    {
        float pv[16];
#pragma unroll
        for (int k = 0; k < 16; k++) pv[k] = p4s[tid + k];
        float lin = 0.f;
#pragma unroll
        for (int k = 0; k < 16; k++) lin = fmaf(v1s[k], pv[k], lin);
        float x2[6];
#pragma unroll
        for (int j = 0; j < 6; j++) {
            float a = 0.f;
#pragma unroll
            for (int k = 0; k < 16; k++) a = fmaf(v2s[j][k], pv[k], a);
            x2[j] = a;
        }
        float quad = x2[0] * x2[3] + x2[1] * x2[4] + x2[2] * x2[5];
        out[b * TLEN + t0 + tid] = lin + quad;
    }
}

// ==================== host launch ==========================================
extern "C" void kernel_launch(void* const* d_in, const int* in_sizes, int n_in,
                              void* d_out, int out_size) {
    const float* x       = (const float*)d_in[0];
    const float* conv1_w = (const float*)d_in[1];
    const float* res_w1  = (const float*)d_in[2];
    const float* res_w2  = (const float*)d_in[3];
    const float* post2_w = (const float*)d_in[4];
    const float* post3_w = (const float*)d_in[5];
    const float* post4_w = (const float*)d_in[6];
    const float* vnn1_w  = (const float*)d_in[7];
    const float* vnn2_w  = (const float*)d_in[8];
    float* out = (float*)d_out;

    uint32_t *bh0, *bl0, *bh1, *bl1;
    uint32_t *w1h, *w1l, *w2h, *w2l;
    cudaGetSymbolAddress((void**)&bh0, g_bh0);
    cudaGetSymbolAddress((void**)&bl0, g_bl0);
    cudaGetSymbolAddress((void**)&bh1, g_bh1);
    cudaGetSymbolAddress((void**)&bl1, g_bl1);
    cudaGetSymbolAddress((void**)&w1h, g_w1h);
    cudaGetSymbolAddress((void**)&w1l, g_w1l);
    cudaGetSymbolAddress((void**)&w2h, g_w2h);
    cudaGetSymbolAddress((void**)&w2l, g_w2l);

    cudaFuncSetAttribute(k_layer, cudaFuncAttributeMaxDynamicSharedMemorySize,
                         SMEM_LAYER_BYTES);

    dim3 grid(TLEN / 128, BATCH);   // 250 x 8

    k_wprep<<<10, TT>>>(res_w1, res_w2);
    k_front<<<grid, TT>>>(x, conv1_w);

    const uint32_t *hinH = bh0, *hinL = bl0;
    uint32_t *houtH = bh1, *houtL = bl1;
    for (int s = 0; s < 2; s++) {
        for (int i = 0; i < 10; i++) {
            k_layer<<<grid, TLT, SMEM_LAYER_BYTES>>>(
                hinH, hinL, houtH, houtL,
                w1h + (size_t)i * 64 * 52, w1l + (size_t)i * 64 * 52,
                w2h + (size_t)i * 64 * 20, w2l + (size_t)i * 64 * 20,
                1 << i);
            const uint32_t* th = houtH; const uint32_t* tl = houtL;
            houtH = (uint32_t*)hinH; houtL = (uint32_t*)hinL;
            hinH = th; hinL = tl;
        }
    }

    k_post<<<grid, TT>>>(post2_w, post3_w, post4_w, vnn1_w, vnn2_w, out);
}